// round 1
// baseline (speedup 1.0000x reference)
#include <cuda_runtime.h>
#include <math.h>

#define D_MODEL 1024
#define N_HEADS 16
#define HEAD_DIM 64
#define BATCH 4
#define SEQ 2048
#define M_TOTAL (BATCH * SEQ)   // 8192

// Scratch (b, h, t, d) layout: index ((b*16+h)*2048 + t)*64 + d
__device__ float g_Q[BATCH * N_HEADS * SEQ * HEAD_DIM];
__device__ float g_K[BATCH * N_HEADS * SEQ * HEAD_DIM];
__device__ float g_V[BATCH * N_HEADS * SEQ * HEAD_DIM];
__device__ float g_O[BATCH * N_HEADS * SEQ * HEAD_DIM];

// ---------------------------------------------------------------------------
// GEMM 1: qkv = x @ W_qkv^T + b_qkv, scattered into g_Q/g_K/g_V (b,h,t,d)
// M=8192, N=3072, K=1024. 64x64 tile, BK=16, 256 threads, 4x4 per thread.
// ---------------------------------------------------------------------------
__global__ __launch_bounds__(256) void gemm_qkv_kernel(
    const float* __restrict__ X,      // (8192, 1024)
    const float* __restrict__ W,      // (3072, 1024) row-major (out, in)
    const float* __restrict__ bias)   // (3072,)
{
    __shared__ float As[64][17];
    __shared__ float Bs[64][17];

    const int tid = threadIdx.x;
    const int n0 = blockIdx.x * 64;
    const int m0 = blockIdx.y * 64;
    const int ty = tid >> 4;          // 0..15
    const int tx = tid & 15;          // 0..15
    const int lr = tid >> 2;          // 0..63 (load row)
    const int lc = (tid & 3) << 2;    // 0,4,8,12 (load col)

    float acc[4][4];
#pragma unroll
    for (int i = 0; i < 4; i++)
#pragma unroll
        for (int j = 0; j < 4; j++) acc[i][j] = 0.f;

    for (int k0 = 0; k0 < D_MODEL; k0 += 16) {
        float4 av = *(const float4*)(X + (size_t)(m0 + lr) * D_MODEL + k0 + lc);
        float4 bv = *(const float4*)(W + (size_t)(n0 + lr) * D_MODEL + k0 + lc);
        As[lr][lc + 0] = av.x; As[lr][lc + 1] = av.y;
        As[lr][lc + 2] = av.z; As[lr][lc + 3] = av.w;
        Bs[lr][lc + 0] = bv.x; Bs[lr][lc + 1] = bv.y;
        Bs[lr][lc + 2] = bv.z; Bs[lr][lc + 3] = bv.w;
        __syncthreads();
#pragma unroll
        for (int kk = 0; kk < 16; kk++) {
            float a[4], b[4];
#pragma unroll
            for (int i = 0; i < 4; i++) a[i] = As[ty * 4 + i][kk];
#pragma unroll
            for (int j = 0; j < 4; j++) b[j] = Bs[tx * 4 + j][kk];
#pragma unroll
            for (int i = 0; i < 4; i++)
#pragma unroll
                for (int j = 0; j < 4; j++) acc[i][j] += a[i] * b[j];
        }
        __syncthreads();
    }

    // Epilogue: scatter into Q/K/V (b,h,t,d). Whole tile has same "which"/head.
    const int which = n0 / D_MODEL;                 // 0=Q,1=K,2=V
    const int h = (n0 % D_MODEL) / HEAD_DIM;        // head (constant per tile)
    float* dst = (which == 0) ? g_Q : (which == 1) ? g_K : g_V;

#pragma unroll
    for (int i = 0; i < 4; i++) {
        const int m = m0 + ty * 4 + i;
        const int b_ = m >> 11;        // /2048
        const int t = m & 2047;
        float* row = dst + ((size_t)(b_ * N_HEADS + h) * SEQ + t) * HEAD_DIM;
#pragma unroll
        for (int j = 0; j < 4; j++) {
            const int o = n0 + tx * 4 + j;
            row[(tx * 4 + j)] = acc[i][j] + bias[o];   // d = tx*4+j since n0%64==0
        }
    }
}

// ---------------------------------------------------------------------------
// Flash attention: per block = (qtile of 64, bh). 256 threads.
// Each thread: query row r = tid/4, group lane g = tid%4.
//   S: owns k-range [g*8, g*8+8) of the 32-wide key tile.
//   O: owns output dims [g*16, g*16+16).
// ---------------------------------------------------------------------------
__global__ __launch_bounds__(256) void attn_kernel()
{
    __shared__ float Qs[64][65];
    __shared__ float Ks[32][65];
    __shared__ float Vs[32][65];
    __shared__ float Ps[64][33];

    const int q0 = blockIdx.x * 64;
    const int bh = blockIdx.y;
    const int tid = threadIdx.x;
    const int r = tid >> 2;
    const int g = tid & 3;

    const float* Qg = g_Q + (size_t)bh * SEQ * HEAD_DIM;
    const float* Kg = g_K + (size_t)bh * SEQ * HEAD_DIM;
    const float* Vg = g_V + (size_t)bh * SEQ * HEAD_DIM;

    // Load Q tile, fold in softmax scale 1/sqrt(64) = 0.125
    for (int idx = tid; idx < 64 * 64; idx += 256) {
        int rr = idx >> 6, cc = idx & 63;
        Qs[rr][cc] = Qg[(size_t)(q0 + rr) * HEAD_DIM + cc] * 0.125f;
    }

    float m = -1e30f, l = 0.f;
    float o[16];
#pragma unroll
    for (int j = 0; j < 16; j++) o[j] = 0.f;

    const int qglob = q0 + r;
    const int nkt = (q0 + 64) / 32;

    for (int jt = 0; jt < nkt; jt++) {
        const int j0 = jt * 32;
        __syncthreads();   // protects Ks/Vs from prior-iter readers
        for (int idx = tid; idx < 32 * 64; idx += 256) {
            int rr = idx >> 6, cc = idx & 63;
            Ks[rr][cc] = Kg[(size_t)(j0 + rr) * HEAD_DIM + cc];
            Vs[rr][cc] = Vg[(size_t)(j0 + rr) * HEAD_DIM + cc];
        }
        __syncthreads();

        float s[8];
        float tmax = -1e30f;
#pragma unroll
        for (int kk = 0; kk < 8; kk++) {
            const int kl = g * 8 + kk;
            float acc = 0.f;
#pragma unroll
            for (int d = 0; d < 64; d++) acc += Qs[r][d] * Ks[kl][d];
            if (j0 + kl > qglob) acc = -1e30f;
            s[kk] = acc;
            tmax = fmaxf(tmax, acc);
        }
        // reduce max over 4-thread group (lanes 4-aligned, xor 1/2 stays in group)
        tmax = fmaxf(tmax, __shfl_xor_sync(0xffffffffu, tmax, 1));
        tmax = fmaxf(tmax, __shfl_xor_sync(0xffffffffu, tmax, 2));

        const float newm = fmaxf(m, tmax);
        const float alpha = __expf(m - newm);
        float lsum = 0.f;
#pragma unroll
        for (int kk = 0; kk < 8; kk++) {
            float p = __expf(s[kk] - newm);
            Ps[r][g * 8 + kk] = p;
            lsum += p;
        }
        lsum += __shfl_xor_sync(0xffffffffu, lsum, 1);
        lsum += __shfl_xor_sync(0xffffffffu, lsum, 2);
        l = l * alpha + lsum;
        m = newm;
#pragma unroll
        for (int j = 0; j < 16; j++) o[j] *= alpha;

        __syncwarp();  // Ps row written by 4 same-warp threads, read by same 4

#pragma unroll
        for (int k = 0; k < 32; k++) {
            const float p = Ps[r][k];
            const float* vrow = &Vs[k][g * 16];
#pragma unroll
            for (int j = 0; j < 16; j++) o[j] += p * vrow[j];
        }
    }

    const float inv = 1.0f / l;
    float* Og = g_O + (size_t)bh * SEQ * HEAD_DIM;
#pragma unroll
    for (int j = 0; j < 16; j++)
        Og[(size_t)qglob * HEAD_DIM + g * 16 + j] = o[j] * inv;
}

// ---------------------------------------------------------------------------
// GEMM 2: out = y @ W_proj^T + b_proj, with y gathered from g_O (b,h,t,d).
// M=8192, N=1024, K=1024.
// ---------------------------------------------------------------------------
__global__ __launch_bounds__(256) void gemm_proj_kernel(
    const float* __restrict__ W,      // (1024, 1024)
    const float* __restrict__ bias,   // (1024,)
    float* __restrict__ out)          // (8192, 1024)
{
    __shared__ float As[64][17];
    __shared__ float Bs[64][17];

    const int tid = threadIdx.x;
    const int n0 = blockIdx.x * 64;
    const int m0 = blockIdx.y * 64;
    const int ty = tid >> 4;
    const int tx = tid & 15;
    const int lr = tid >> 2;
    const int lc = (tid & 3) << 2;

    // A-row gather coords (constant over k loop)
    const int am = m0 + lr;
    const int ab = am >> 11;
    const int at = am & 2047;

    float acc[4][4];
#pragma unroll
    for (int i = 0; i < 4; i++)
#pragma unroll
        for (int j = 0; j < 4; j++) acc[i][j] = 0.f;

    for (int k0 = 0; k0 < D_MODEL; k0 += 16) {
        const int c = k0 + lc;
        const int h = c >> 6;
        const int dd = c & 63;
        float4 av = *(const float4*)(g_O +
            ((size_t)(ab * N_HEADS + h) * SEQ + at) * HEAD_DIM + dd);
        float4 bv = *(const float4*)(W + (size_t)(n0 + lr) * D_MODEL + k0 + lc);
        As[lr][lc + 0] = av.x; As[lr][lc + 1] = av.y;
        As[lr][lc + 2] = av.z; As[lr][lc + 3] = av.w;
        Bs[lr][lc + 0] = bv.x; Bs[lr][lc + 1] = bv.y;
        Bs[lr][lc + 2] = bv.z; Bs[lr][lc + 3] = bv.w;
        __syncthreads();
#pragma unroll
        for (int kk = 0; kk < 16; kk++) {
            float a[4], b[4];
#pragma unroll
            for (int i = 0; i < 4; i++) a[i] = As[ty * 4 + i][kk];
#pragma unroll
            for (int j = 0; j < 4; j++) b[j] = Bs[tx * 4 + j][kk];
#pragma unroll
            for (int i = 0; i < 4; i++)
#pragma unroll
                for (int j = 0; j < 4; j++) acc[i][j] += a[i] * b[j];
        }
        __syncthreads();
    }

#pragma unroll
    for (int i = 0; i < 4; i++) {
        const int mm = m0 + ty * 4 + i;
#pragma unroll
        for (int j = 0; j < 4; j++) {
            const int oo = n0 + tx * 4 + j;
            out[(size_t)mm * D_MODEL + oo] = acc[i][j] + bias[oo];
        }
    }
}

// ---------------------------------------------------------------------------
extern "C" void kernel_launch(void* const* d_in, const int* in_sizes, int n_in,
                              void* d_out, int out_size)
{
    const float* x      = (const float*)d_in[0];   // (4,2048,1024)
    const float* W_qkv  = (const float*)d_in[1];   // (3072,1024)
    const float* b_qkv  = (const float*)d_in[2];   // (3072,)
    const float* W_proj = (const float*)d_in[3];   // (1024,1024)
    const float* b_proj = (const float*)d_in[4];   // (1024,)
    float* out = (float*)d_out;

    (void)in_sizes; (void)n_in; (void)out_size;

    gemm_qkv_kernel<<<dim3(3 * D_MODEL / 64, M_TOTAL / 64), 256>>>(x, W_qkv, b_qkv);
    attn_kernel<<<dim3(SEQ / 64, BATCH * N_HEADS), 256>>>();
    gemm_proj_kernel<<<dim3(D_MODEL / 64, M_TOTAL / 64), 256>>>(W_proj, b_proj, out);
}

// round 2
// speedup vs baseline: 2.1290x; 2.1290x over previous
#include <cuda_runtime.h>
#include <math.h>

#define D_MODEL 1024
#define N_HEADS 16
#define HEAD_DIM 64
#define BATCH 4
#define SEQ 2048
#define M_TOTAL (BATCH * SEQ)   // 8192

// Scratch (b, h, t, d) layout: index ((b*16+h)*2048 + t)*64 + d
__device__ float g_Q[BATCH * N_HEADS * SEQ * HEAD_DIM];
__device__ float g_K[BATCH * N_HEADS * SEQ * HEAD_DIM];
__device__ float g_V[BATCH * N_HEADS * SEQ * HEAD_DIM];
__device__ float g_O[BATCH * N_HEADS * SEQ * HEAD_DIM];

// ---------------------------------------------------------------------------
// GEMM 1: qkv = x @ W_qkv^T + b_qkv, scattered into g_Q/g_K/g_V (b,h,t,d)
// M=8192, N=3072, K=1024. 128x128 tile, BK=16, 256 threads, 8x8 per thread.
// Smem stored k-major (transposed) so the microkernel uses LDS.128.
// ---------------------------------------------------------------------------
__global__ __launch_bounds__(256, 2) void gemm_qkv_kernel(
    const float* __restrict__ X,      // (8192, 1024)
    const float* __restrict__ W,      // (3072, 1024) row-major (out, in)
    const float* __restrict__ bias)   // (3072,)
{
    __shared__ float As[16][132];     // [k][m], 132*4 bytes = 16B-aligned rows
    __shared__ float Bs[16][132];     // [k][n]

    const int tid = threadIdx.x;
    const int n0 = blockIdx.x * 128;
    const int m0 = blockIdx.y * 128;
    const int lrow = tid >> 2;          // 0..63
    const int lc4  = (tid & 3) << 2;    // 0,4,8,12
    const int ms = (tid >> 4) << 3;     // 0..120
    const int ns = (tid & 15) << 3;     // 0..120

    const float* Arow0 = X + (size_t)(m0 + lrow) * D_MODEL + lc4;
    const float* Arow1 = Arow0 + (size_t)64 * D_MODEL;
    const float* Brow0 = W + (size_t)(n0 + lrow) * D_MODEL + lc4;
    const float* Brow1 = Brow0 + (size_t)64 * D_MODEL;

    float acc[8][8] = {};

    float4 pa0 = *(const float4*)(Arow0);
    float4 pa1 = *(const float4*)(Arow1);
    float4 pb0 = *(const float4*)(Brow0);
    float4 pb1 = *(const float4*)(Brow1);

    for (int k0 = 0; k0 < D_MODEL; k0 += 16) {
        // stage current tile into smem (transposed)
        As[lc4 + 0][lrow] = pa0.x; As[lc4 + 1][lrow] = pa0.y;
        As[lc4 + 2][lrow] = pa0.z; As[lc4 + 3][lrow] = pa0.w;
        As[lc4 + 0][lrow + 64] = pa1.x; As[lc4 + 1][lrow + 64] = pa1.y;
        As[lc4 + 2][lrow + 64] = pa1.z; As[lc4 + 3][lrow + 64] = pa1.w;
        Bs[lc4 + 0][lrow] = pb0.x; Bs[lc4 + 1][lrow] = pb0.y;
        Bs[lc4 + 2][lrow] = pb0.z; Bs[lc4 + 3][lrow] = pb0.w;
        Bs[lc4 + 0][lrow + 64] = pb1.x; Bs[lc4 + 1][lrow + 64] = pb1.y;
        Bs[lc4 + 2][lrow + 64] = pb1.z; Bs[lc4 + 3][lrow + 64] = pb1.w;
        __syncthreads();

        // prefetch next tile (latency overlapped with compute below)
        if (k0 + 16 < D_MODEL) {
            pa0 = *(const float4*)(Arow0 + k0 + 16);
            pa1 = *(const float4*)(Arow1 + k0 + 16);
            pb0 = *(const float4*)(Brow0 + k0 + 16);
            pb1 = *(const float4*)(Brow1 + k0 + 16);
        }

#pragma unroll
        for (int kk = 0; kk < 16; kk++) {
            float4 xa0 = *(const float4*)&As[kk][ms];
            float4 xa1 = *(const float4*)&As[kk][ms + 4];
            float4 xb0 = *(const float4*)&Bs[kk][ns];
            float4 xb1 = *(const float4*)&Bs[kk][ns + 4];
            float a[8] = {xa0.x, xa0.y, xa0.z, xa0.w, xa1.x, xa1.y, xa1.z, xa1.w};
            float b[8] = {xb0.x, xb0.y, xb0.z, xb0.w, xb1.x, xb1.y, xb1.z, xb1.w};
#pragma unroll
            for (int i = 0; i < 8; i++)
#pragma unroll
                for (int j = 0; j < 8; j++) acc[i][j] += a[i] * b[j];
        }
        __syncthreads();
    }

    // Epilogue: scatter into Q/K/V (b,h,t,d). ns block of 8 cols lies in one head.
    const int col0 = n0 + ns;
    const int which = col0 >> 10;                 // 0=Q,1=K,2=V
    const int h = (col0 & 1023) >> 6;
    const int d0 = col0 & 63;
    float* dst = (which == 0) ? g_Q : (which == 1) ? g_K : g_V;

    float bj[8];
#pragma unroll
    for (int j = 0; j < 8; j++) bj[j] = bias[col0 + j];

#pragma unroll
    for (int i = 0; i < 8; i++) {
        const int mrow = m0 + ms + i;
        const int b_ = mrow >> 11;
        const int t = mrow & 2047;
        float* rp = dst + ((size_t)(b_ * N_HEADS + h) * SEQ + t) * HEAD_DIM + d0;
#pragma unroll
        for (int j = 0; j < 8; j++) rp[j] = acc[i][j] + bj[j];
    }
}

// ---------------------------------------------------------------------------
// Flash attention: block = (qtile 64, bh), 256 threads.
// Two GEMM phases with 4x4 register frags and transposed smem (LDS.128 feeds).
//   S: thread (ty,tx) owns q rows ty*4..+3, k cols tx*4..+3, contraction over d.
//   O: thread owns q rows ty*4..+3, d cols tx*4..+3, contraction over k (via Pt).
// Row stats (m,l) replicated across the 16 tx lanes of each ty group.
// ---------------------------------------------------------------------------
#define AT_STRIDE 68
__global__ __launch_bounds__(256) void attn_kernel()
{
    extern __shared__ float smr[];
    float (*Qt)[AT_STRIDE] = (float(*)[AT_STRIDE])(smr);                  // [d][q]
    float (*Kt)[AT_STRIDE] = (float(*)[AT_STRIDE])(smr + 64 * AT_STRIDE);  // [d][k]
    float (*Vs)[AT_STRIDE] = (float(*)[AT_STRIDE])(smr + 2 * 64 * AT_STRIDE); // [k][d]
    float (*Pt)[AT_STRIDE] = (float(*)[AT_STRIDE])(smr + 3 * 64 * AT_STRIDE); // [k][q]

    const int q0 = blockIdx.x * 64;
    const int bh = blockIdx.y;
    const int tid = threadIdx.x;
    const int tx = tid & 15;
    const int ty = tid >> 4;
    const int qs = ty << 2;      // q sub-rows
    const int cs = tx << 2;      // k cols (S phase) / d cols (O phase)

    const float* Qg = g_Q + (size_t)bh * SEQ * HEAD_DIM;
    const float* Kg = g_K + (size_t)bh * SEQ * HEAD_DIM;
    const float* Vg = g_V + (size_t)bh * SEQ * HEAD_DIM;

    // Load Q tile transposed, fold in softmax scale 1/sqrt(64)=0.125
    for (int idx = tid; idx < 64 * 16; idx += 256) {
        const int qr = idx >> 4;
        const int c4 = (idx & 15) << 2;
        float4 v = *(const float4*)(Qg + (size_t)(q0 + qr) * HEAD_DIM + c4);
        Qt[c4 + 0][qr] = v.x * 0.125f;
        Qt[c4 + 1][qr] = v.y * 0.125f;
        Qt[c4 + 2][qr] = v.z * 0.125f;
        Qt[c4 + 3][qr] = v.w * 0.125f;
    }

    float mx[4], lx[4];
    float o[4][4] = {};
#pragma unroll
    for (int i = 0; i < 4; i++) { mx[i] = -1e30f; lx[i] = 0.f; }

    const int nkt = q0 / 64 + 1;
    for (int jt = 0; jt < nkt; jt++) {
        const int j0 = jt * 64;
        __syncthreads();   // prior-iter readers of Kt/Vs done; also covers Qt init
        for (int idx = tid; idx < 64 * 16; idx += 256) {
            const int kr = idx >> 4;
            const int c4 = (idx & 15) << 2;
            float4 kv = *(const float4*)(Kg + (size_t)(j0 + kr) * HEAD_DIM + c4);
            float4 vv = *(const float4*)(Vg + (size_t)(j0 + kr) * HEAD_DIM + c4);
            Kt[c4 + 0][kr] = kv.x; Kt[c4 + 1][kr] = kv.y;
            Kt[c4 + 2][kr] = kv.z; Kt[c4 + 3][kr] = kv.w;
            *(float4*)&Vs[kr][c4] = vv;
        }
        __syncthreads();

        // ---- S = Q @ K^T (4x4 frag, contraction over d) ----
        float s[4][4] = {};
#pragma unroll
        for (int d = 0; d < 64; d++) {
            float4 a = *(const float4*)&Qt[d][qs];
            float4 b = *(const float4*)&Kt[d][cs];
            float av[4] = {a.x, a.y, a.z, a.w};
            float bv[4] = {b.x, b.y, b.z, b.w};
#pragma unroll
            for (int i = 0; i < 4; i++)
#pragma unroll
                for (int j = 0; j < 4; j++) s[i][j] += av[i] * bv[j];
        }

        // causal mask
#pragma unroll
        for (int i = 0; i < 4; i++)
#pragma unroll
            for (int j = 0; j < 4; j++)
                if (j0 + cs + j > q0 + qs + i) s[i][j] = -1e30f;

        // ---- online softmax ----
        float tmax[4];
#pragma unroll
        for (int i = 0; i < 4; i++)
            tmax[i] = fmaxf(fmaxf(s[i][0], s[i][1]), fmaxf(s[i][2], s[i][3]));
#pragma unroll
        for (int off = 1; off < 16; off <<= 1)
#pragma unroll
            for (int i = 0; i < 4; i++)
                tmax[i] = fmaxf(tmax[i], __shfl_xor_sync(0xffffffffu, tmax[i], off));

        float p[4][4], lsum[4];
#pragma unroll
        for (int i = 0; i < 4; i++) {
            const float newm = fmaxf(mx[i], tmax[i]);
            const float alpha = __expf(mx[i] - newm);
            float ls = 0.f;
#pragma unroll
            for (int j = 0; j < 4; j++) { p[i][j] = __expf(s[i][j] - newm); ls += p[i][j]; }
            lsum[i] = ls;
            mx[i] = newm;
            lx[i] *= alpha;
#pragma unroll
            for (int j = 0; j < 4; j++) o[i][j] *= alpha;
        }
#pragma unroll
        for (int off = 1; off < 16; off <<= 1)
#pragma unroll
            for (int i = 0; i < 4; i++)
                lsum[i] += __shfl_xor_sync(0xffffffffu, lsum[i], off);
#pragma unroll
        for (int i = 0; i < 4; i++) lx[i] += lsum[i];

        // store P transposed (register transpose -> 4x STS.128)
#pragma unroll
        for (int j = 0; j < 4; j++) {
            float4 col = make_float4(p[0][j], p[1][j], p[2][j], p[3][j]);
            *(float4*)&Pt[cs + j][qs] = col;
        }
        __syncthreads();

        // ---- O += P @ V (4x4 frag, contraction over k) ----
#pragma unroll
        for (int k = 0; k < 64; k++) {
            float4 a = *(const float4*)&Pt[k][qs];
            float4 b = *(const float4*)&Vs[k][cs];
            float av[4] = {a.x, a.y, a.z, a.w};
            float bv[4] = {b.x, b.y, b.z, b.w};
#pragma unroll
            for (int i = 0; i < 4; i++)
#pragma unroll
                for (int j = 0; j < 4; j++) o[i][j] += av[i] * bv[j];
        }
    }

    float* Og = g_O + (size_t)bh * SEQ * HEAD_DIM;
#pragma unroll
    for (int i = 0; i < 4; i++) {
        const float inv = 1.0f / lx[i];
        float4 r = make_float4(o[i][0] * inv, o[i][1] * inv, o[i][2] * inv, o[i][3] * inv);
        *(float4*)(Og + (size_t)(q0 + qs + i) * HEAD_DIM + cs) = r;
    }
}

// ---------------------------------------------------------------------------
// GEMM 2: out = y @ W_proj^T + b_proj, y gathered from g_O (b,h,t,d).
// M=8192, N=1024, K=1024. Same 128x128x16 / 8x8 structure.
// ---------------------------------------------------------------------------
__global__ __launch_bounds__(256, 2) void gemm_proj_kernel(
    const float* __restrict__ W,      // (1024, 1024)
    const float* __restrict__ bias,   // (1024,)
    float* __restrict__ out)          // (8192, 1024)
{
    __shared__ float As[16][132];
    __shared__ float Bs[16][132];

    const int tid = threadIdx.x;
    const int n0 = blockIdx.x * 128;
    const int m0 = blockIdx.y * 128;
    const int lrow = tid >> 2;
    const int lc4  = (tid & 3) << 2;
    const int ms = (tid >> 4) << 3;
    const int ns = (tid & 15) << 3;

    const int am0 = m0 + lrow;
    const int ab0 = am0 >> 11, at0 = am0 & 2047;
    const int am1 = am0 + 64;
    const int ab1 = am1 >> 11, at1 = am1 & 2047;

    const float* Brow0 = W + (size_t)(n0 + lrow) * D_MODEL + lc4;
    const float* Brow1 = Brow0 + (size_t)64 * D_MODEL;

    float acc[8][8] = {};

    // A gather address for k-chunk: col c = k0 + lc4; h = c>>6; d = c&63
    int c = lc4;
    float4 pa0 = *(const float4*)(g_O + ((size_t)(ab0 * N_HEADS + (c >> 6)) * SEQ + at0) * HEAD_DIM + (c & 63));
    float4 pa1 = *(const float4*)(g_O + ((size_t)(ab1 * N_HEADS + (c >> 6)) * SEQ + at1) * HEAD_DIM + (c & 63));
    float4 pb0 = *(const float4*)(Brow0);
    float4 pb1 = *(const float4*)(Brow1);

    for (int k0 = 0; k0 < D_MODEL; k0 += 16) {
        As[lc4 + 0][lrow] = pa0.x; As[lc4 + 1][lrow] = pa0.y;
        As[lc4 + 2][lrow] = pa0.z; As[lc4 + 3][lrow] = pa0.w;
        As[lc4 + 0][lrow + 64] = pa1.x; As[lc4 + 1][lrow + 64] = pa1.y;
        As[lc4 + 2][lrow + 64] = pa1.z; As[lc4 + 3][lrow + 64] = pa1.w;
        Bs[lc4 + 0][lrow] = pb0.x; Bs[lc4 + 1][lrow] = pb0.y;
        Bs[lc4 + 2][lrow] = pb0.z; Bs[lc4 + 3][lrow] = pb0.w;
        Bs[lc4 + 0][lrow + 64] = pb1.x; Bs[lc4 + 1][lrow + 64] = pb1.y;
        Bs[lc4 + 2][lrow + 64] = pb1.z; Bs[lc4 + 3][lrow + 64] = pb1.w;
        __syncthreads();

        if (k0 + 16 < D_MODEL) {
            c = k0 + 16 + lc4;
            const int h = c >> 6, dd = c & 63;
            pa0 = *(const float4*)(g_O + ((size_t)(ab0 * N_HEADS + h) * SEQ + at0) * HEAD_DIM + dd);
            pa1 = *(const float4*)(g_O + ((size_t)(ab1 * N_HEADS + h) * SEQ + at1) * HEAD_DIM + dd);
            pb0 = *(const float4*)(Brow0 + k0 + 16);
            pb1 = *(const float4*)(Brow1 + k0 + 16);
        }

#pragma unroll
        for (int kk = 0; kk < 16; kk++) {
            float4 xa0 = *(const float4*)&As[kk][ms];
            float4 xa1 = *(const float4*)&As[kk][ms + 4];
            float4 xb0 = *(const float4*)&Bs[kk][ns];
            float4 xb1 = *(const float4*)&Bs[kk][ns + 4];
            float a[8] = {xa0.x, xa0.y, xa0.z, xa0.w, xa1.x, xa1.y, xa1.z, xa1.w};
            float b[8] = {xb0.x, xb0.y, xb0.z, xb0.w, xb1.x, xb1.y, xb1.z, xb1.w};
#pragma unroll
            for (int i = 0; i < 8; i++)
#pragma unroll
                for (int j = 0; j < 8; j++) acc[i][j] += a[i] * b[j];
        }
        __syncthreads();
    }

    float bj[8];
#pragma unroll
    for (int j = 0; j < 8; j++) bj[j] = bias[n0 + ns + j];

#pragma unroll
    for (int i = 0; i < 8; i++) {
        const int mrow = m0 + ms + i;
        float* rp = out + (size_t)mrow * D_MODEL + n0 + ns;
#pragma unroll
        for (int j = 0; j < 8; j++) rp[j] = acc[i][j] + bj[j];
    }
}

// ---------------------------------------------------------------------------
extern "C" void kernel_launch(void* const* d_in, const int* in_sizes, int n_in,
                              void* d_out, int out_size)
{
    const float* x      = (const float*)d_in[0];   // (4,2048,1024)
    const float* W_qkv  = (const float*)d_in[1];   // (3072,1024)
    const float* b_qkv  = (const float*)d_in[2];   // (3072,)
    const float* W_proj = (const float*)d_in[3];   // (1024,1024)
    const float* b_proj = (const float*)d_in[4];   // (1024,)
    float* out = (float*)d_out;

    (void)in_sizes; (void)n_in; (void)out_size;

    const int attn_smem = 4 * 64 * AT_STRIDE * (int)sizeof(float);  // 69632 B
    cudaFuncSetAttribute(attn_kernel, cudaFuncAttributeMaxDynamicSharedMemorySize, attn_smem);

    gemm_qkv_kernel<<<dim3(3 * D_MODEL / 128, M_TOTAL / 128), 256>>>(x, W_qkv, b_qkv);
    attn_kernel<<<dim3(SEQ / 64, BATCH * N_HEADS), 256, attn_smem>>>();
    gemm_proj_kernel<<<dim3(D_MODEL / 128, M_TOTAL / 128), 256>>>(W_proj, b_proj, out);
}

// round 4
// speedup vs baseline: 5.6035x; 2.6320x over previous
#include <cuda_runtime.h>
#include <cuda_bf16.h>
#include <math.h>
#include <stdint.h>
#include <string.h>

#define D_MODEL 1024
#define N_HEADS 16
#define HEAD_DIM 64
#define BATCH 4
#define SEQ 2048
#define M_TOTAL 8192
#define BHD (BATCH * N_HEADS * SEQ * HEAD_DIM)

// ---------------------------------------------------------------------------
// Device scratch (no allocs allowed)
// ---------------------------------------------------------------------------
__device__ __align__(16) __nv_bfloat16 g_xhi[M_TOTAL * D_MODEL];
__device__ __align__(16) __nv_bfloat16 g_xlo[M_TOTAL * D_MODEL];
__device__ __align__(16) __nv_bfloat16 g_wqkv_hi[3 * D_MODEL * D_MODEL];
__device__ __align__(16) __nv_bfloat16 g_wqkv_lo[3 * D_MODEL * D_MODEL];
__device__ __align__(16) __nv_bfloat16 g_wproj_hi[D_MODEL * D_MODEL];
__device__ __align__(16) __nv_bfloat16 g_wproj_lo[D_MODEL * D_MODEL];
// (b,h,t,d) layout
__device__ __align__(16) __nv_bfloat16 g_Qhi[BHD];
__device__ __align__(16) __nv_bfloat16 g_Qlo[BHD];
__device__ __align__(16) __nv_bfloat16 g_Khi[BHD];
__device__ __align__(16) __nv_bfloat16 g_Klo[BHD];
__device__ __align__(16) __nv_bfloat16 g_Vhi[BHD];
__device__ __align__(16) __nv_bfloat16 g_Vlo[BHD];
__device__ __align__(16) __nv_bfloat16 g_Ohi[BHD];
__device__ __align__(16) __nv_bfloat16 g_Olo[BHD];

// ---------------------------------------------------------------------------
// Helpers: all baseline PTX (sm_80-level) — NO tcgen05 (ptxas target lacks 'a')
// ---------------------------------------------------------------------------
__device__ __forceinline__ uint32_t smem_u32(const void* p) {
    uint32_t a;
    asm("{ .reg .u64 t; cvta.to.shared.u64 t, %1; cvt.u32.u64 %0, t; }"
        : "=r"(a) : "l"(p));
    return a;
}

#define CP16(dst, src) \
    asm volatile("cp.async.cg.shared.global [%0], [%1], 16;\n" :: "r"(dst), "l"(src))
#define CP_COMMIT asm volatile("cp.async.commit_group;\n" ::: "memory")
#define CP_WAIT1  asm volatile("cp.async.wait_group 1;\n" ::: "memory")
#define CP_WAIT0  asm volatile("cp.async.wait_group 0;\n" ::: "memory")

__device__ __forceinline__ void ldsm4(uint32_t* r, uint32_t a) {
    asm volatile("ldmatrix.sync.aligned.m8n8.x4.shared.b16 {%0,%1,%2,%3}, [%4];\n"
        : "=r"(r[0]), "=r"(r[1]), "=r"(r[2]), "=r"(r[3]) : "r"(a));
}
__device__ __forceinline__ void ldsm4t(uint32_t* r, uint32_t a) {
    asm volatile("ldmatrix.sync.aligned.m8n8.x4.trans.shared.b16 {%0,%1,%2,%3}, [%4];\n"
        : "=r"(r[0]), "=r"(r[1]), "=r"(r[2]), "=r"(r[3]) : "r"(a));
}
__device__ __forceinline__ void mma16816(float* c, const uint32_t* a,
                                         uint32_t b0, uint32_t b1) {
    asm volatile(
        "mma.sync.aligned.m16n8k16.row.col.f32.bf16.bf16.f32 "
        "{%0,%1,%2,%3}, {%4,%5,%6,%7}, {%8,%9}, {%0,%1,%2,%3};\n"
        : "+f"(c[0]), "+f"(c[1]), "+f"(c[2]), "+f"(c[3])
        : "r"(a[0]), "r"(a[1]), "r"(a[2]), "r"(a[3]), "r"(b0), "r"(b1));
}

__device__ __forceinline__ uint32_t pk2(__nv_bfloat16 a, __nv_bfloat16 b) {
    __nv_bfloat162 t; t.x = a; t.y = b;
    uint32_t r; memcpy(&r, &t, 4); return r;
}

__device__ __forceinline__ void store_split2(__nv_bfloat16* hi, __nv_bfloat16* lo,
                                             size_t idx, float v0, float v1) {
    __nv_bfloat16 h0 = __float2bfloat16_rn(v0);
    __nv_bfloat16 h1 = __float2bfloat16_rn(v1);
    __nv_bfloat162 H; H.x = h0; H.y = h1;
    __nv_bfloat162 L;
    L.x = __float2bfloat16_rn(v0 - __bfloat162float(h0));
    L.y = __float2bfloat16_rn(v1 - __bfloat162float(h1));
    *(__nv_bfloat162*)(hi + idx) = H;
    *(__nv_bfloat162*)(lo + idx) = L;
}

// ---------------------------------------------------------------------------
// f32 -> (bf16 hi, bf16 lo residual)
// ---------------------------------------------------------------------------
__global__ void cvt_pair_kernel(const float* __restrict__ src,
                                __nv_bfloat16* __restrict__ hi,
                                __nv_bfloat16* __restrict__ lo, int n4)
{
    for (int i = blockIdx.x * blockDim.x + threadIdx.x; i < n4;
         i += gridDim.x * blockDim.x) {
        float4 v = *(const float4*)(src + (size_t)i * 4);
        __nv_bfloat16 h0 = __float2bfloat16_rn(v.x), h1 = __float2bfloat16_rn(v.y);
        __nv_bfloat16 h2 = __float2bfloat16_rn(v.z), h3 = __float2bfloat16_rn(v.w);
        __nv_bfloat162* ph = (__nv_bfloat162*)(hi + (size_t)i * 4);
        __nv_bfloat162* pl = (__nv_bfloat162*)(lo + (size_t)i * 4);
        __nv_bfloat162 a, b, c, d;
        a.x = h0; a.y = h1; b.x = h2; b.y = h3;
        c.x = __float2bfloat16_rn(v.x - __bfloat162float(h0));
        c.y = __float2bfloat16_rn(v.y - __bfloat162float(h1));
        d.x = __float2bfloat16_rn(v.z - __bfloat162float(h2));
        d.y = __float2bfloat16_rn(v.w - __bfloat162float(h3));
        ph[0] = a; ph[1] = b; pl[0] = c; pl[1] = d;
    }
}

// ---------------------------------------------------------------------------
// Split-bf16 tensor-core GEMM: C(8192, N) = A @ B^T + bias
// CTA 128x128, BK=32, 8 warps (2x4), warp tile 64x32, m16n8k16 fragments.
// mode 0: A = x hi/lo, B = W_qkv; epilogue -> g_{Q,K,V}{hi,lo} (b,h,t,d), Q*0.125
// mode 1: A = attn O hi/lo gathered from (b,h,t,d), B = W_proj; out fp32.
// ---------------------------------------------------------------------------
#define GK 32
#define GSTRIDE 80          // bytes per smem row (40 bf16, conflict-free ldmatrix)
#define GA_HI 0
#define GA_LO 10240
#define GB_HI 20480
#define GB_LO 30720
#define GSTAGE 40960
#define GEMM_SMEM (2 * GSTAGE)

__device__ __forceinline__ void gemm_load(
    uint32_t smb, int st,
    const __nv_bfloat16* __restrict__ Ahi, const __nv_bfloat16* __restrict__ Alo,
    const __nv_bfloat16* __restrict__ Bhi, const __nv_bfloat16* __restrict__ Blo,
    int m0, int n0, int k0, int tid, int mode)
{
    const uint32_t dst0 = smb + st * GSTAGE;
#pragma unroll
    for (int i = tid; i < 512; i += 256) {
        const int r = i >> 2, u = i & 3;
        size_t src;
        if (mode == 0) {
            src = (size_t)(m0 + r) * D_MODEL + k0 + u * 8;
        } else {
            const int m = m0 + r, b = m >> 11, t = m & 2047;
            src = ((size_t)(b * 16 + (k0 >> 6)) * SEQ + t) * 64 + (k0 & 63) + u * 8;
        }
        const uint32_t d = dst0 + (uint32_t)(r * GSTRIDE + u * 16);
        CP16(d + GA_HI, Ahi + src);
        CP16(d + GA_LO, Alo + src);
    }
#pragma unroll
    for (int i = tid; i < 512; i += 256) {
        const int r = i >> 2, u = i & 3;
        const size_t src = (size_t)(n0 + r) * D_MODEL + k0 + u * 8;
        const uint32_t d = dst0 + (uint32_t)(r * GSTRIDE + u * 16);
        CP16(d + GB_HI, Bhi + src);
        CP16(d + GB_LO, Blo + src);
    }
}

__global__ __launch_bounds__(256) void gemm_mma_kernel(
    const __nv_bfloat16* __restrict__ Ahi, const __nv_bfloat16* __restrict__ Alo,
    const __nv_bfloat16* __restrict__ Bhi, const __nv_bfloat16* __restrict__ Blo,
    const float* __restrict__ bias, float* __restrict__ outp, int mode)
{
    extern __shared__ char sm[];
    const uint32_t smb = smem_u32(sm);
    const int tid = threadIdx.x, lane = tid & 31, wid = tid >> 5;
    const int wm = wid >> 2, wn = wid & 3;
    const int n0 = blockIdx.x * 128, m0 = blockIdx.y * 128;

    float c[4][4][4] = {};

    gemm_load(smb, 0, Ahi, Alo, Bhi, Blo, m0, n0, 0, tid, mode);
    CP_COMMIT;

    const uint32_t aB = smb + (uint32_t)((wm * 64 + (lane & 15)) * GSTRIDE + (lane >> 4) * 16);
    const uint32_t bB = smb + GB_HI +
        (uint32_t)((wn * 32 + ((lane >> 4) << 3) + (lane & 7)) * GSTRIDE + ((lane >> 3) & 1) * 16);

    for (int ch = 0; ch < D_MODEL / GK; ++ch) {
        const int s = ch & 1;
        if (ch + 1 < D_MODEL / GK) {
            gemm_load(smb, s ^ 1, Ahi, Alo, Bhi, Blo, m0, n0, (ch + 1) * GK, tid, mode);
            CP_COMMIT;
            CP_WAIT1;
        } else {
            CP_WAIT0;
        }
        __syncthreads();
        const uint32_t so = s * GSTAGE;
#pragma unroll
        for (int ks = 0; ks < 2; ++ks) {
            uint32_t ah[4][4], al[4][4];
#pragma unroll
            for (int mi = 0; mi < 4; mi++) {
                const uint32_t a = aB + so + mi * 16 * GSTRIDE + ks * 32;
                ldsm4(ah[mi], a + GA_HI);
                ldsm4(al[mi], a + GA_LO);
            }
            uint32_t bhf[2][4], blf[2][4];
#pragma unroll
            for (int np = 0; np < 2; np++) {
                const uint32_t a = bB + so + np * 16 * GSTRIDE + ks * 32;
                ldsm4(bhf[np], a);
                ldsm4(blf[np], a + (GB_LO - GB_HI));
            }
#pragma unroll
            for (int mi = 0; mi < 4; mi++)
#pragma unroll
                for (int nt = 0; nt < 4; nt++) {
                    const uint32_t b0h = bhf[nt >> 1][(nt & 1) * 2];
                    const uint32_t b1h = bhf[nt >> 1][(nt & 1) * 2 + 1];
                    const uint32_t b0l = blf[nt >> 1][(nt & 1) * 2];
                    const uint32_t b1l = blf[nt >> 1][(nt & 1) * 2 + 1];
                    mma16816(c[mi][nt], ah[mi], b0h, b1h);
                    mma16816(c[mi][nt], ah[mi], b0l, b1l);
                    mma16816(c[mi][nt], al[mi], b0h, b1h);
                }
        }
        __syncthreads();
    }

    // Epilogue
#pragma unroll
    for (int mi = 0; mi < 4; mi++)
#pragma unroll
        for (int nt = 0; nt < 4; nt++) {
            const int col = n0 + wn * 32 + nt * 8 + (lane & 3) * 2;
            const float bv0 = __ldg(bias + col), bv1 = __ldg(bias + col + 1);
            const int mA = m0 + wm * 64 + mi * 16 + (lane >> 2);
            if (mode == 1) {
                float2 r0 = make_float2(c[mi][nt][0] + bv0, c[mi][nt][1] + bv1);
                float2 r1 = make_float2(c[mi][nt][2] + bv0, c[mi][nt][3] + bv1);
                *(float2*)(outp + (size_t)mA * D_MODEL + col) = r0;
                *(float2*)(outp + (size_t)(mA + 8) * D_MODEL + col) = r1;
            } else {
                const int which = col >> 10, h = (col >> 6) & 15, d = col & 63;
                __nv_bfloat16* dh = (which == 0) ? g_Qhi : (which == 1) ? g_Khi : g_Vhi;
                __nv_bfloat16* dl = (which == 0) ? g_Qlo : (which == 1) ? g_Klo : g_Vlo;
                const float sc = (which == 0) ? 0.125f : 1.0f;
#pragma unroll
                for (int half = 0; half < 2; half++) {
                    const int m = mA + half * 8;
                    const int b = m >> 11, t = m & 2047;
                    const size_t idx = ((size_t)(b * 16 + h) * SEQ + t) * 64 + d;
                    store_split2(dh, dl, idx,
                                 (c[mi][nt][half * 2 + 0] + bv0) * sc,
                                 (c[mi][nt][half * 2 + 1] + bv1) * sc);
                }
            }
        }
}

// ---------------------------------------------------------------------------
// Flash attention, tensor-core version.
// Block: (q-tile 128, bh), 8 warps; each warp owns 16 q rows.
// kv-tile 64. S and PV via m16n8k16 bf16 MMA, 3-term split precision.
// P fragments converted in-register (C-frag layout == A-frag layout).
// ---------------------------------------------------------------------------
#define AST 144             // smem row stride bytes (72 bf16)
#define AQ_HI 0
#define AQ_LO 18432
#define AKV0 36864
#define AKV_STAGE 36864
#define AK_HI 0
#define AK_LO 9216
#define AV_HI 18432
#define AV_LO 27648
#define ATTN_SMEM (AKV0 + 2 * AKV_STAGE)   // 110592

__device__ __forceinline__ void attn_loadkv(
    uint32_t smb, int st,
    const __nv_bfloat16* __restrict__ Kh, const __nv_bfloat16* __restrict__ Kl,
    const __nv_bfloat16* __restrict__ Vh, const __nv_bfloat16* __restrict__ Vl,
    int j0, int tid)
{
    const uint32_t dst0 = smb + AKV0 + st * AKV_STAGE;
#pragma unroll
    for (int i = tid; i < 512; i += 256) {
        const int r = i >> 3, u = i & 7;
        const size_t src = (size_t)(j0 + r) * 64 + u * 8;
        const uint32_t d = dst0 + (uint32_t)(r * AST + u * 16);
        CP16(d + AK_HI, Kh + src);
        CP16(d + AK_LO, Kl + src);
        CP16(d + AV_HI, Vh + src);
        CP16(d + AV_LO, Vl + src);
    }
}

__global__ __launch_bounds__(256) void attn_mma_kernel()
{
    extern __shared__ char sm[];
    const uint32_t smb = smem_u32(sm);
    const int tid = threadIdx.x, lane = tid & 31, wid = tid >> 5;
    const int q0 = blockIdx.x * 128;
    const int bh = blockIdx.y;
    const size_t bhoff = (size_t)bh * SEQ * HEAD_DIM;

    const __nv_bfloat16* Qh = g_Qhi + bhoff;
    const __nv_bfloat16* Ql = g_Qlo + bhoff;
    const __nv_bfloat16* Kh = g_Khi + bhoff;
    const __nv_bfloat16* Kl = g_Klo + bhoff;
    const __nv_bfloat16* Vh = g_Vhi + bhoff;
    const __nv_bfloat16* Vl = g_Vlo + bhoff;

    // Stage Q (plain loads)
#pragma unroll
    for (int i = tid; i < 1024; i += 256) {
        const int r = i >> 3, u = i & 7;
        const size_t src = (size_t)(q0 + r) * 64 + u * 8;
        *(uint4*)(sm + AQ_HI + r * AST + u * 16) = *(const uint4*)(Qh + src);
        *(uint4*)(sm + AQ_LO + r * AST + u * 16) = *(const uint4*)(Ql + src);
    }
    attn_loadkv(smb, 0, Kh, Kl, Vh, Vl, 0, tid);
    CP_COMMIT;
    __syncthreads();

    // Q fragments (held for whole kernel)
    uint32_t qh[4][4], ql[4][4];
    {
        const uint32_t base = smb +
            (uint32_t)((wid * 16 + (lane & 15)) * AST + (lane >> 4) * 16);
#pragma unroll
        for (int kc = 0; kc < 4; kc++) {
            ldsm4(qh[kc], base + AQ_HI + kc * 32);
            ldsm4(ql[kc], base + AQ_LO + kc * 32);
        }
    }

    float o[8][4] = {};
    float mxA = -1e30f, mxB = -1e30f, lxA = 0.f, lxB = 0.f;
    const int nkt = blockIdx.x * 2 + 2;
    const int qA = q0 + wid * 16 + (lane >> 2);

    for (int jt = 0; jt < nkt; ++jt) {
        const int s = jt & 1;
        if (jt + 1 < nkt) {
            attn_loadkv(smb, s ^ 1, Kh, Kl, Vh, Vl, (jt + 1) * 64, tid);
            CP_COMMIT;
            CP_WAIT1;
        } else {
            CP_WAIT0;
        }
        __syncthreads();
        const uint32_t kvb = smb + AKV0 + s * AKV_STAGE;

        // ---- S = Q @ K^T ----
        float sfr[8][4] = {};
        {
            const uint32_t kb = kvb +
                (uint32_t)((((lane >> 4) << 3) + (lane & 7)) * AST + ((lane >> 3) & 1) * 16);
#pragma unroll
            for (int kc = 0; kc < 4; kc++) {
                uint32_t kfh[4][4], kfl[4][4];
#pragma unroll
                for (int np = 0; np < 4; np++) {
                    const uint32_t a = kb + np * 16 * AST + kc * 32;
                    ldsm4(kfh[np], a + AK_HI);
                    ldsm4(kfl[np], a + AK_LO);
                }
#pragma unroll
                for (int nt = 0; nt < 8; nt++) {
                    const uint32_t b0h = kfh[nt >> 1][(nt & 1) * 2];
                    const uint32_t b1h = kfh[nt >> 1][(nt & 1) * 2 + 1];
                    const uint32_t b0l = kfl[nt >> 1][(nt & 1) * 2];
                    const uint32_t b1l = kfl[nt >> 1][(nt & 1) * 2 + 1];
                    mma16816(sfr[nt], qh[kc], b0h, b1h);
                    mma16816(sfr[nt], qh[kc], b0l, b1l);
                    mma16816(sfr[nt], ql[kc], b0h, b1h);
                }
            }
        }

        // Causal mask
        const int j0 = jt * 64;
#pragma unroll
        for (int nt = 0; nt < 8; nt++) {
            const int c0 = j0 + nt * 8 + (lane & 3) * 2;
            if (c0 > qA)     sfr[nt][0] = -1e30f;
            if (c0 + 1 > qA) sfr[nt][1] = -1e30f;
            if (c0 > qA + 8)     sfr[nt][2] = -1e30f;
            if (c0 + 1 > qA + 8) sfr[nt][3] = -1e30f;
        }

        // Online softmax
        float tA = -1e30f, tB = -1e30f;
#pragma unroll
        for (int nt = 0; nt < 8; nt++) {
            tA = fmaxf(tA, fmaxf(sfr[nt][0], sfr[nt][1]));
            tB = fmaxf(tB, fmaxf(sfr[nt][2], sfr[nt][3]));
        }
        tA = fmaxf(tA, __shfl_xor_sync(0xffffffffu, tA, 1));
        tA = fmaxf(tA, __shfl_xor_sync(0xffffffffu, tA, 2));
        tB = fmaxf(tB, __shfl_xor_sync(0xffffffffu, tB, 1));
        tB = fmaxf(tB, __shfl_xor_sync(0xffffffffu, tB, 2));

        const float nmA = fmaxf(mxA, tA), nmB = fmaxf(mxB, tB);
        const float aA = __expf(mxA - nmA), aB = __expf(mxB - nmB);
        mxA = nmA; mxB = nmB;

        float lsA = 0.f, lsB = 0.f;
        uint32_t aph[4][4], apl[4][4];
#pragma unroll
        for (int nt = 0; nt < 8; nt++) {
            const float p0 = __expf(sfr[nt][0] - nmA);
            const float p1 = __expf(sfr[nt][1] - nmA);
            const float p2 = __expf(sfr[nt][2] - nmB);
            const float p3 = __expf(sfr[nt][3] - nmB);
            lsA += p0 + p1; lsB += p2 + p3;
            const __nv_bfloat16 h0 = __float2bfloat16_rn(p0);
            const __nv_bfloat16 h1 = __float2bfloat16_rn(p1);
            const __nv_bfloat16 h2 = __float2bfloat16_rn(p2);
            const __nv_bfloat16 h3 = __float2bfloat16_rn(p3);
            aph[nt >> 1][(nt & 1) * 2 + 0] = pk2(h0, h1);
            aph[nt >> 1][(nt & 1) * 2 + 1] = pk2(h2, h3);
            apl[nt >> 1][(nt & 1) * 2 + 0] =
                pk2(__float2bfloat16_rn(p0 - __bfloat162float(h0)),
                    __float2bfloat16_rn(p1 - __bfloat162float(h1)));
            apl[nt >> 1][(nt & 1) * 2 + 1] =
                pk2(__float2bfloat16_rn(p2 - __bfloat162float(h2)),
                    __float2bfloat16_rn(p3 - __bfloat162float(h3)));
        }
        lsA += __shfl_xor_sync(0xffffffffu, lsA, 1);
        lsA += __shfl_xor_sync(0xffffffffu, lsA, 2);
        lsB += __shfl_xor_sync(0xffffffffu, lsB, 1);
        lsB += __shfl_xor_sync(0xffffffffu, lsB, 2);
        lxA = lxA * aA + lsA;
        lxB = lxB * aB + lsB;
#pragma unroll
        for (int dn = 0; dn < 8; dn++) {
            o[dn][0] *= aA; o[dn][1] *= aA;
            o[dn][2] *= aB; o[dn][3] *= aB;
        }

        // ---- O += P @ V ----
        {
            const uint32_t vb = kvb + AV_HI +
                (uint32_t)((((lane >> 3) & 1) * 8 + (lane & 7)) * AST + (lane >> 4) * 16);
#pragma unroll
            for (int kc = 0; kc < 4; kc++) {
                uint32_t vfh[4][4], vfl[4][4];
#pragma unroll
                for (int dp = 0; dp < 4; dp++) {
                    const uint32_t a = vb + kc * 16 * AST + dp * 32;
                    ldsm4t(vfh[dp], a);
                    ldsm4t(vfl[dp], a + (AV_LO - AV_HI));
                }
#pragma unroll
                for (int dn = 0; dn < 8; dn++) {
                    const uint32_t b0h = vfh[dn >> 1][(dn & 1) * 2];
                    const uint32_t b1h = vfh[dn >> 1][(dn & 1) * 2 + 1];
                    const uint32_t b0l = vfl[dn >> 1][(dn & 1) * 2];
                    const uint32_t b1l = vfl[dn >> 1][(dn & 1) * 2 + 1];
                    mma16816(o[dn], aph[kc], b0h, b1h);
                    mma16816(o[dn], aph[kc], b0l, b1l);
                    mma16816(o[dn], apl[kc], b0h, b1h);
                }
            }
        }
        __syncthreads();
    }

    // Epilogue: normalize, split to bf16 hi/lo, write O (b,h,t,d)
    const float invA = 1.0f / lxA, invB = 1.0f / lxB;
    const int tA_ = q0 + wid * 16 + (lane >> 2);
    const int tB_ = tA_ + 8;
#pragma unroll
    for (int dn = 0; dn < 8; dn++) {
        const int d = dn * 8 + (lane & 3) * 2;
        store_split2(g_Ohi, g_Olo, bhoff + (size_t)tA_ * 64 + d,
                     o[dn][0] * invA, o[dn][1] * invA);
        store_split2(g_Ohi, g_Olo, bhoff + (size_t)tB_ * 64 + d,
                     o[dn][2] * invB, o[dn][3] * invB);
    }
}

// ---------------------------------------------------------------------------
extern "C" void kernel_launch(void* const* d_in, const int* in_sizes, int n_in,
                              void* d_out, int out_size)
{
    const float* x      = (const float*)d_in[0];
    const float* W_qkv  = (const float*)d_in[1];
    const float* b_qkv  = (const float*)d_in[2];
    const float* W_proj = (const float*)d_in[3];
    const float* b_proj = (const float*)d_in[4];
    float* out = (float*)d_out;

    (void)in_sizes; (void)n_in; (void)out_size;

    cudaFuncSetAttribute(gemm_mma_kernel,
                         cudaFuncAttributeMaxDynamicSharedMemorySize, GEMM_SMEM);
    cudaFuncSetAttribute(attn_mma_kernel,
                         cudaFuncAttributeMaxDynamicSharedMemorySize, ATTN_SMEM);

    __nv_bfloat16 *xhi, *xlo, *wqh, *wql, *wph, *wpl, *ohi, *olo;
    cudaGetSymbolAddress((void**)&xhi, g_xhi);
    cudaGetSymbolAddress((void**)&xlo, g_xlo);
    cudaGetSymbolAddress((void**)&wqh, g_wqkv_hi);
    cudaGetSymbolAddress((void**)&wql, g_wqkv_lo);
    cudaGetSymbolAddress((void**)&wph, g_wproj_hi);
    cudaGetSymbolAddress((void**)&wpl, g_wproj_lo);
    cudaGetSymbolAddress((void**)&ohi, g_Ohi);
    cudaGetSymbolAddress((void**)&olo, g_Olo);

    cvt_pair_kernel<<<1024, 256>>>(x, xhi, xlo, M_TOTAL * D_MODEL / 4);
    cvt_pair_kernel<<<1024, 256>>>(W_qkv, wqh, wql, 3 * D_MODEL * D_MODEL / 4);
    cvt_pair_kernel<<<512, 256>>>(W_proj, wph, wpl, D_MODEL * D_MODEL / 4);

    gemm_mma_kernel<<<dim3(3 * D_MODEL / 128, M_TOTAL / 128), 256, GEMM_SMEM>>>(
        xhi, xlo, wqh, wql, b_qkv, nullptr, 0);

    attn_mma_kernel<<<dim3(SEQ / 128, BATCH * N_HEADS), 256, ATTN_SMEM>>>();

    gemm_mma_kernel<<<dim3(D_MODEL / 128, M_TOTAL / 128), 256, GEMM_SMEM>>>(
        ohi, olo, wph, wpl, b_proj, out, 1);
}